// round 4
// baseline (speedup 1.0000x reference)
#include <cuda_runtime.h>
#include <cuda_bf16.h>

#define IN_DIM 4
#define H_DIM 30
#define N_UNIT 100
#define TPB 256

__global__ __launch_bounds__(TPB) void e2e_mlp_dispatch_kernel(
    const float* __restrict__ x,
    const float* __restrict__ Cost,
    const float* __restrict__ Pmax,
    const float* __restrict__ Pd,
    const float* __restrict__ wcap,
    const float* __restrict__ W1,
    const float* __restrict__ b1,
    const float* __restrict__ W2,
    const float* __restrict__ b2,
    const float* __restrict__ W3,
    const float* __restrict__ b3,
    float* __restrict__ out,
    int B)
{
    __shared__ float sW1[IN_DIM * H_DIM];
    __shared__ float sb1[H_DIM];
    __shared__ float sW2[H_DIM * H_DIM];
    __shared__ float sb2[H_DIM];
    __shared__ float sW3[H_DIM];
    __shared__ float sCost[N_UNIT];
    __shared__ float sPmax[N_UNIT];
    __shared__ float sCum[N_UNIT];
    __shared__ float sTd[TPB];
    __shared__ float sb3v, sSumPd, sWcap;

    const int t = threadIdx.x;

    // ---- stage small tensors into shared ----
    for (int i = t; i < IN_DIM * H_DIM; i += TPB) sW1[i] = W1[i];
    for (int i = t; i < H_DIM * H_DIM; i += TPB) sW2[i] = W2[i];
    if (t < H_DIM) { sb1[t] = b1[t]; sb2[t] = b2[t]; sW3[t] = W3[t]; }
    if (t == 0) { sb3v = b3[0]; sWcap = wcap[0]; }
    for (int i = t; i < N_UNIT; i += TPB) { sCost[i] = Cost[i]; sPmax[i] = Pmax[i]; }
    __syncthreads();

    // ---- exclusive cumulative capacity of strictly-cheaper units (stable rank),
    //      directly in ORIGINAL unit order: no sort, no scatter needed ----
    if (t < N_UNIT) {
        const float c = sCost[t];
        float s = 0.0f;
        #pragma unroll 4
        for (int j = 0; j < N_UNIT; ++j) {
            const float cj = sCost[j];
            if (cj < c || (cj == c && j < t)) s += sPmax[j];
        }
        sCum[t] = s;
    }
    if (t == 0) {
        float s = 0.0f;
        #pragma unroll 4
        for (int j = 0; j < N_UNIT; ++j) s += Pd[j];
        sSumPd = s;
    }
    __syncthreads();

    // ---- MLP: one thread = one batch row ----
    const int b = blockIdx.x * TPB + t;
    float4 xv = make_float4(0.f, 0.f, 0.f, 0.f);
    if (b < B) xv = *reinterpret_cast<const float4*>(x + 4ll * b);

    float h1[H_DIM];
    #pragma unroll
    for (int j = 0; j < H_DIM; ++j) {
        float a = sb1[j];
        a = fmaf(xv.x, sW1[0 * H_DIM + j], a);
        a = fmaf(xv.y, sW1[1 * H_DIM + j], a);
        a = fmaf(xv.z, sW1[2 * H_DIM + j], a);
        a = fmaf(xv.w, sW1[3 * H_DIM + j], a);
        h1[j] = fmaxf(a, 0.0f);
    }

    float y = sb3v;
    #pragma unroll
    for (int j = 0; j < H_DIM; ++j) {
        float a = sb2[j];
        #pragma unroll
        for (int k = 0; k < H_DIM; ++k)
            a = fmaf(h1[k], sW2[k * H_DIM + j], a);
        y = fmaf(fmaxf(a, 0.0f), sW3[j], y);
    }

    sTd[t] = sSumPd - sWcap * y;   // residual demand for this row
    __syncthreads();

    // ---- cooperative coalesced store of the block's contiguous [TPB x N_UNIT] slab ----
    const long long base = (long long)blockIdx.x * TPB * N_UNIT;
    const long long total = (long long)B * N_UNIT;
    const int slab_vec = TPB * N_UNIT / 4;   // 6400 float4s
    float4* out4 = reinterpret_cast<float4*>(out + base);

    for (int i = t; i < slab_vec; i += TPB) {
        const int off = i * 4;
        if (base + off >= total) break;
        float4 v;
        float* pv = &v.x;
        #pragma unroll
        for (int j = 0; j < 4; ++j) {
            const int o = off + j;
            const int row = o / N_UNIT;
            const int u = o - row * N_UNIT;
            const float p = sTd[row] - sCum[u];
            pv[j] = fminf(fmaxf(p, 0.0f), sPmax[u]);
        }
        out4[i] = v;
    }
}

extern "C" void kernel_launch(void* const* d_in, const int* in_sizes, int n_in,
                              void* d_out, int out_size) {
    const float* x    = (const float*)d_in[0];
    const float* Cost = (const float*)d_in[1];
    const float* Pmax = (const float*)d_in[2];
    const float* Pd   = (const float*)d_in[3];
    const float* wcap = (const float*)d_in[4];
    const float* W1   = (const float*)d_in[5];
    const float* b1   = (const float*)d_in[6];
    const float* W2   = (const float*)d_in[7];
    const float* b2   = (const float*)d_in[8];
    const float* W3   = (const float*)d_in[9];
    const float* b3   = (const float*)d_in[10];
    float* out = (float*)d_out;

    const int B = in_sizes[0] / IN_DIM;
    const int grid = (B + TPB - 1) / TPB;
    e2e_mlp_dispatch_kernel<<<grid, TPB>>>(x, Cost, Pmax, Pd, wcap,
                                           W1, b1, W2, b2, W3, b3, out, B);
}

// round 8
// speedup vs baseline: 1.3302x; 1.3302x over previous
#include <cuda_runtime.h>
#include <cuda_bf16.h>

#define IN_DIM 4
#define H_DIM 30
#define N_UNIT 100
#define B_MAX 262144

#define K1_TPB 256
#define K2_TPB 800          // 25 warps; t%25 = fixed unit-group, t/25 = row lane
#define K2_ROWS 512         // rows per block; 512*25/800 = 16 iterations

__device__ float g_td[B_MAX];   // residual demand per batch row (scratch)

// ---------------------------------------------------------------------------
// K1: MLP 4->30->30->1, one thread per row, writes Td[b] = sumPd - wcap*y
// ---------------------------------------------------------------------------
__global__ __launch_bounds__(K1_TPB) void k1_mlp(
    const float* __restrict__ x,
    const float* __restrict__ Pd,
    const float* __restrict__ wcap,
    const float* __restrict__ W1,
    const float* __restrict__ b1,
    const float* __restrict__ W2,
    const float* __restrict__ b2,
    const float* __restrict__ W3,
    const float* __restrict__ b3,
    int B)
{
    __shared__ float sW1[IN_DIM * H_DIM];
    __shared__ float sb1[H_DIM];
    __shared__ float sW2[H_DIM * H_DIM];
    __shared__ float sb2[H_DIM];
    __shared__ float sW3[H_DIM];
    __shared__ float sb3v, sSumPd, sWcap;

    const int t = threadIdx.x;
    for (int i = t; i < IN_DIM * H_DIM; i += K1_TPB) sW1[i] = W1[i];
    for (int i = t; i < H_DIM * H_DIM; i += K1_TPB) sW2[i] = W2[i];
    if (t < H_DIM) { sb1[t] = b1[t]; sb2[t] = b2[t]; sW3[t] = W3[t]; }
    if (t == 0) {
        sb3v = b3[0]; sWcap = wcap[0];
        float s = 0.0f;
        #pragma unroll 4
        for (int j = 0; j < N_UNIT; ++j) s += Pd[j];
        sSumPd = s;
    }
    __syncthreads();

    const int b = blockIdx.x * K1_TPB + t;
    if (b >= B) return;
    const float4 xv = *reinterpret_cast<const float4*>(x + 4ll * b);

    float h1[H_DIM];
    #pragma unroll
    for (int j = 0; j < H_DIM; ++j) {
        float a = sb1[j];
        a = fmaf(xv.x, sW1[0 * H_DIM + j], a);
        a = fmaf(xv.y, sW1[1 * H_DIM + j], a);
        a = fmaf(xv.z, sW1[2 * H_DIM + j], a);
        a = fmaf(xv.w, sW1[3 * H_DIM + j], a);
        h1[j] = fmaxf(a, 0.0f);
    }

    float y = sb3v;
    #pragma unroll
    for (int j = 0; j < H_DIM; ++j) {
        float a = sb2[j];
        #pragma unroll
        for (int k = 0; k < H_DIM; ++k)
            a = fmaf(h1[k], sW2[k * H_DIM + j], a);
        y = fmaf(fmaxf(a, 0.0f), sW3[j], y);
    }

    g_td[b] = sSumPd - sWcap * y;
}

// ---------------------------------------------------------------------------
// K2: dispatch writer. Block covers K2_ROWS rows x 100 units.
// Thread owns fixed unit-group g=t%25 -> cum4/pmax4 stay in REGISTERS.
// Per iteration: 1 LDS (Td) + 8 FADD/FMNMX + 1 STG.128, fully coalesced.
// ---------------------------------------------------------------------------
__global__ __launch_bounds__(K2_TPB) void k2_dispatch(
    const float* __restrict__ Cost,
    const float* __restrict__ Pmax,
    float* __restrict__ out,
    int B)
{
    __shared__ float sCost[N_UNIT];
    __shared__ float sPmax[N_UNIT];
    __shared__ float sCum[N_UNIT];
    __shared__ float sTd[K2_ROWS];

    const int t = threadIdx.x;
    if (t < N_UNIT) { sCost[t] = Cost[t]; sPmax[t] = Pmax[t]; }
    __syncthreads();

    // exclusive cumulative capacity of strictly-cheaper units (stable rank)
    if (t < N_UNIT) {
        const float c = sCost[t];
        float s = 0.0f;
        #pragma unroll 4
        for (int j = 0; j < N_UNIT; ++j) {
            const float cj = sCost[j];
            if (cj < c || (cj == c && j < t)) s += sPmax[j];
        }
        sCum[t] = s;
    }

    // stage this block's Td rows
    const int rowbase = blockIdx.x * K2_ROWS;
    for (int i = t; i < K2_ROWS; i += K2_TPB) {
        const int r = rowbase + i;
        sTd[i] = (r < B) ? g_td[r] : 0.0f;
    }
    __syncthreads();

    // fixed unit-group for this thread: units [4g, 4g+4)
    const int g  = t % 25;
    const int r0 = t / 25;          // 0..31
    float4 cum4, pm4;
    cum4.x = sCum[4 * g + 0]; cum4.y = sCum[4 * g + 1];
    cum4.z = sCum[4 * g + 2]; cum4.w = sCum[4 * g + 3];
    pm4.x  = sPmax[4 * g + 0]; pm4.y = sPmax[4 * g + 1];
    pm4.z  = sPmax[4 * g + 2]; pm4.w = sPmax[4 * g + 3];

    float4* out4 = reinterpret_cast<float4*>(out);

    #pragma unroll
    for (int k = 0; k < K2_ROWS / 32; ++k) {
        const int rl = r0 + 32 * k;          // local row
        const int r  = rowbase + rl;
        if (r >= B) break;
        const float td = sTd[rl];
        float4 v;
        v.x = fminf(fmaxf(td - cum4.x, 0.0f), pm4.x);
        v.y = fminf(fmaxf(td - cum4.y, 0.0f), pm4.y);
        v.z = fminf(fmaxf(td - cum4.z, 0.0f), pm4.z);
        v.w = fminf(fmaxf(td - cum4.w, 0.0f), pm4.w);
        out4[(long long)r * 25 + g] = v;
    }
}

extern "C" void kernel_launch(void* const* d_in, const int* in_sizes, int n_in,
                              void* d_out, int out_size) {
    const float* x    = (const float*)d_in[0];
    const float* Cost = (const float*)d_in[1];
    const float* Pmax = (const float*)d_in[2];
    const float* Pd   = (const float*)d_in[3];
    const float* wcap = (const float*)d_in[4];
    const float* W1   = (const float*)d_in[5];
    const float* b1   = (const float*)d_in[6];
    const float* W2   = (const float*)d_in[7];
    const float* b2   = (const float*)d_in[8];
    const float* W3   = (const float*)d_in[9];
    const float* b3   = (const float*)d_in[10];
    float* out = (float*)d_out;

    const int B = in_sizes[0] / IN_DIM;

    const int grid1 = (B + K1_TPB - 1) / K1_TPB;
    k1_mlp<<<grid1, K1_TPB>>>(x, Pd, wcap, W1, b1, W2, b2, W3, b3, B);

    const int grid2 = (B + K2_ROWS - 1) / K2_ROWS;
    k2_dispatch<<<grid2, K2_TPB>>>(Cost, Pmax, out, B);
}

// round 9
// speedup vs baseline: 1.3675x; 1.0281x over previous
#include <cuda_runtime.h>
#include <cuda_bf16.h>

#define IN_DIM 4
#define H_DIM 30
#define N_UNIT 100
#define B_MAX 262144

#define K1_TPB 128
#define K1_RPT 4            // rows per thread (2 f32x2 pairs)

#define K2_TPB 800          // 25 warps; t%25 = fixed unit-group, t/25 = row lane
#define K2_ROWS 128         // rows per block -> grid 2048, many waves, small tail

typedef unsigned long long u64;

__device__ float g_td[B_MAX];   // residual demand per batch row (scratch)

// ---- packed f32x2 helpers (Blackwell sm_103a) ----
__device__ __forceinline__ u64 f2_fma(u64 a, u64 b, u64 c) {
    u64 d;
    asm("fma.rn.f32x2 %0, %1, %2, %3;" : "=l"(d) : "l"(a), "l"(b), "l"(c));
    return d;
}
__device__ __forceinline__ u64 f2_pack(float lo, float hi) {
    u64 d;
    asm("mov.b64 %0, {%1, %2};" : "=l"(d) : "f"(lo), "f"(hi));
    return d;
}
__device__ __forceinline__ void f2_unpack(u64 v, float& lo, float& hi) {
    asm("mov.b64 {%0, %1}, %2;" : "=f"(lo), "=f"(hi) : "l"(v));
}
__device__ __forceinline__ u64 f2_relu(u64 v) {
    float lo, hi;
    f2_unpack(v, lo, hi);
    return f2_pack(fmaxf(lo, 0.0f), fmaxf(hi, 0.0f));
}
__device__ __forceinline__ u64 splat_bits(float w) {
    unsigned u = __float_as_uint(w);
    return (u64)u | ((u64)u << 32);
}

// ---------------------------------------------------------------------------
// K1: MLP 4->30->30->1, 4 rows/thread via packed f32x2 FMA.
// Weights pre-splatted to (w,w) u64 in shared: 1 LDS.64 -> 2 FFMA2 (4 rows).
// ---------------------------------------------------------------------------
__global__ __launch_bounds__(K1_TPB, 3) void k1_mlp(
    const float* __restrict__ x,
    const float* __restrict__ Pd,
    const float* __restrict__ wcap,
    const float* __restrict__ W1,
    const float* __restrict__ b1,
    const float* __restrict__ W2,
    const float* __restrict__ b2,
    const float* __restrict__ W3,
    const float* __restrict__ b3,
    int B)
{
    __shared__ u64 sW1d[IN_DIM * H_DIM];
    __shared__ u64 sB1d[H_DIM];
    __shared__ u64 sW2d[H_DIM * H_DIM];
    __shared__ u64 sB2d[H_DIM];
    __shared__ u64 sW3d[H_DIM];
    __shared__ float sSumPd, sWcap, sB3;

    const int t = threadIdx.x;
    for (int i = t; i < IN_DIM * H_DIM; i += K1_TPB) sW1d[i] = splat_bits(W1[i]);
    for (int i = t; i < H_DIM * H_DIM; i += K1_TPB) sW2d[i] = splat_bits(W2[i]);
    if (t < H_DIM) {
        sB1d[t] = splat_bits(b1[t]);
        sB2d[t] = splat_bits(b2[t]);
        sW3d[t] = splat_bits(W3[t]);
    }
    if (t == 0) {
        sB3 = b3[0]; sWcap = wcap[0];
        float s = 0.0f;
        #pragma unroll 4
        for (int j = 0; j < N_UNIT; ++j) s += Pd[j];
        sSumPd = s;
    }
    __syncthreads();

    const int rb = (blockIdx.x * K1_TPB + t) * K1_RPT;
    if (rb >= B) return;

    // 4 consecutive rows: 16 consecutive floats, fully coalesced
    const float4 v0 = *reinterpret_cast<const float4*>(x + 4ll * rb);
    const float4 v1 = *reinterpret_cast<const float4*>(x + 4ll * rb + 4);
    const float4 v2 = *reinterpret_cast<const float4*>(x + 4ll * rb + 8);
    const float4 v3 = *reinterpret_cast<const float4*>(x + 4ll * rb + 12);

    u64 xP[IN_DIM], xQ[IN_DIM];
    xP[0] = f2_pack(v0.x, v1.x); xQ[0] = f2_pack(v2.x, v3.x);
    xP[1] = f2_pack(v0.y, v1.y); xQ[1] = f2_pack(v2.y, v3.y);
    xP[2] = f2_pack(v0.z, v1.z); xQ[2] = f2_pack(v2.z, v3.z);
    xP[3] = f2_pack(v0.w, v1.w); xQ[3] = f2_pack(v2.w, v3.w);

    // layer 1 (j unrolled: h1 must be static register indices)
    u64 h1P[H_DIM], h1Q[H_DIM];
    #pragma unroll
    for (int j = 0; j < H_DIM; ++j) {
        u64 aP = sB1d[j];
        u64 aQ = aP;
        #pragma unroll
        for (int i = 0; i < IN_DIM; ++i) {
            const u64 w = sW1d[i * H_DIM + j];
            aP = f2_fma(xP[i], w, aP);
            aQ = f2_fma(xQ[i], w, aQ);
        }
        h1P[j] = f2_relu(aP);
        h1Q[j] = f2_relu(aQ);
    }

    // layer 2 + output (j rolled to keep I-footprint small, k unrolled)
    u64 yP = f2_pack(sB3, sB3);
    u64 yQ = yP;
    #pragma unroll 1
    for (int j = 0; j < H_DIM; ++j) {
        u64 aP = sB2d[j];
        u64 aQ = aP;
        #pragma unroll
        for (int k = 0; k < H_DIM; ++k) {
            const u64 w = sW2d[k * H_DIM + j];
            aP = f2_fma(h1P[k], w, aP);
            aQ = f2_fma(h1Q[k], w, aQ);
        }
        const u64 w3 = sW3d[j];
        yP = f2_fma(f2_relu(aP), w3, yP);
        yQ = f2_fma(f2_relu(aQ), w3, yQ);
    }

    float y0, y1, y2, y3;
    f2_unpack(yP, y0, y1);
    f2_unpack(yQ, y2, y3);

    float4 td;
    td.x = sSumPd - sWcap * y0;
    td.y = sSumPd - sWcap * y1;
    td.z = sSumPd - sWcap * y2;
    td.w = sSumPd - sWcap * y3;
    *reinterpret_cast<float4*>(g_td + rb) = td;
}

// ---------------------------------------------------------------------------
// K2: dispatch writer. Thread owns fixed unit-group g=t%25 (cum/pmax in regs).
// Per iteration: 1 LDS + clip + 1 STG.128, fully coalesced. Small blocks of
// 128 rows -> grid 2048 -> no wave-quantization tail.
// ---------------------------------------------------------------------------
__global__ __launch_bounds__(K2_TPB) void k2_dispatch(
    const float* __restrict__ Cost,
    const float* __restrict__ Pmax,
    float* __restrict__ out,
    int B)
{
    __shared__ float sCost[N_UNIT];
    __shared__ float sPmax[N_UNIT];
    __shared__ float sCum[N_UNIT];
    __shared__ float sTd[K2_ROWS];

    const int t = threadIdx.x;
    if (t < N_UNIT) { sCost[t] = Cost[t]; sPmax[t] = Pmax[t]; }
    __syncthreads();

    // exclusive cumulative capacity of strictly-cheaper units (stable rank)
    if (t < N_UNIT) {
        const float c = sCost[t];
        float s = 0.0f;
        #pragma unroll 4
        for (int j = 0; j < N_UNIT; ++j) {
            const float cj = sCost[j];
            if (cj < c || (cj == c && j < t)) s += sPmax[j];
        }
        sCum[t] = s;
    }

    const int rowbase = blockIdx.x * K2_ROWS;
    for (int i = t; i < K2_ROWS; i += K2_TPB) {
        const int r = rowbase + i;
        sTd[i] = (r < B) ? g_td[r] : 0.0f;
    }
    __syncthreads();

    const int g  = t % 25;          // unit-group: units [4g, 4g+4)
    const int r0 = t / 25;          // 0..31
    float4 cum4, pm4;
    cum4.x = sCum[4 * g + 0]; cum4.y = sCum[4 * g + 1];
    cum4.z = sCum[4 * g + 2]; cum4.w = sCum[4 * g + 3];
    pm4.x  = sPmax[4 * g + 0]; pm4.y = sPmax[4 * g + 1];
    pm4.z  = sPmax[4 * g + 2]; pm4.w = sPmax[4 * g + 3];

    float4* out4 = reinterpret_cast<float4*>(out);

    #pragma unroll
    for (int k = 0; k < K2_ROWS / 32; ++k) {
        const int rl = r0 + 32 * k;
        const int r  = rowbase + rl;
        if (r >= B) break;
        const float td = sTd[rl];
        float4 v;
        v.x = fminf(fmaxf(td - cum4.x, 0.0f), pm4.x);
        v.y = fminf(fmaxf(td - cum4.y, 0.0f), pm4.y);
        v.z = fminf(fmaxf(td - cum4.z, 0.0f), pm4.z);
        v.w = fminf(fmaxf(td - cum4.w, 0.0f), pm4.w);
        out4[(long long)r * 25 + g] = v;
    }
}

extern "C" void kernel_launch(void* const* d_in, const int* in_sizes, int n_in,
                              void* d_out, int out_size) {
    const float* x    = (const float*)d_in[0];
    const float* Cost = (const float*)d_in[1];
    const float* Pmax = (const float*)d_in[2];
    const float* Pd   = (const float*)d_in[3];
    const float* wcap = (const float*)d_in[4];
    const float* W1   = (const float*)d_in[5];
    const float* b1   = (const float*)d_in[6];
    const float* W2   = (const float*)d_in[7];
    const float* b2   = (const float*)d_in[8];
    const float* W3   = (const float*)d_in[9];
    const float* b3   = (const float*)d_in[10];
    float* out = (float*)d_out;

    const int B = in_sizes[0] / IN_DIM;

    const int grid1 = (B + K1_TPB * K1_RPT - 1) / (K1_TPB * K1_RPT);
    k1_mlp<<<grid1, K1_TPB>>>(x, Pd, wcap, W1, b1, W2, b2, W3, b3, B);

    const int grid2 = (B + K2_ROWS - 1) / K2_ROWS;
    k2_dispatch<<<grid2, K2_TPB>>>(Cost, Pmax, out, B);
}

// round 10
// speedup vs baseline: 1.5367x; 1.1237x over previous
#include <cuda_runtime.h>
#include <cuda_bf16.h>

#define IN_DIM 4
#define H_DIM 30
#define N_UNIT 100
#define B_MAX 262144

#define K1_TPB 128
#define K1_RPT 2            // rows per thread (one f32x2 pair)

#define K2_TPB 800          // 25 warps; t%25 = fixed unit-group, t/25 = row lane
#define K2_ROWS 256         // rows per block -> grid 1024

typedef unsigned long long u64;

__device__ float g_td[B_MAX];     // residual demand per batch row (scratch)
__device__ float g_cum[N_UNIT];   // exclusive cum. capacity, original unit order
__device__ float g_sumPd;
__device__ float g_wcap;

// ---- packed f32x2 helpers (Blackwell sm_103a) ----
__device__ __forceinline__ u64 f2_fma(u64 a, u64 b, u64 c) {
    u64 d;
    asm("fma.rn.f32x2 %0, %1, %2, %3;" : "=l"(d) : "l"(a), "l"(b), "l"(c));
    return d;
}
__device__ __forceinline__ u64 f2_pack(float lo, float hi) {
    u64 d;
    asm("mov.b64 %0, {%1, %2};" : "=l"(d) : "f"(lo), "f"(hi));
    return d;
}
__device__ __forceinline__ void f2_unpack(u64 v, float& lo, float& hi) {
    asm("mov.b64 {%0, %1}, %2;" : "=f"(lo), "=f"(hi) : "l"(v));
}
__device__ __forceinline__ u64 f2_relu(u64 v) {
    float lo, hi;
    f2_unpack(v, lo, hi);
    return f2_pack(fmaxf(lo, 0.0f), fmaxf(hi, 0.0f));
}
__device__ __forceinline__ u64 splat_bits(float w) {
    unsigned u = __float_as_uint(w);
    return (u64)u | ((u64)u << 32);
}

// ---------------------------------------------------------------------------
// K0: one block. Batch-invariant precompute: rank-cumsum, sum(Pd), wcap.
// ---------------------------------------------------------------------------
__global__ __launch_bounds__(128) void k0_prep(
    const float* __restrict__ Cost,
    const float* __restrict__ Pmax,
    const float* __restrict__ Pd,
    const float* __restrict__ wcap)
{
    __shared__ float sC[N_UNIT], sP[N_UNIT], sPd[N_UNIT];
    const int t = threadIdx.x;
    if (t < N_UNIT) { sC[t] = Cost[t]; sP[t] = Pmax[t]; sPd[t] = Pd[t]; }
    __syncthreads();

    if (t < N_UNIT) {
        const float c = sC[t];
        float s = 0.0f;
        #pragma unroll 4
        for (int j = 0; j < N_UNIT; ++j) {
            const float cj = sC[j];
            if (cj < c || (cj == c && j < t)) s += sP[j];
        }
        g_cum[t] = s;
    }
    if (t == 0) {
        float s = 0.0f;
        #pragma unroll 4
        for (int j = 0; j < N_UNIT; ++j) s += sPd[j];
        g_sumPd = s;
        g_wcap = wcap[0];
    }
}

// ---------------------------------------------------------------------------
// K1: MLP 4->30->30->1, 2 rows/thread via packed f32x2 FMA.
// Weights pre-splatted to (w,w) u64 in shared: 1 LDS.64 feeds 1 FFMA2 (2 rows).
// ---------------------------------------------------------------------------
__global__ __launch_bounds__(K1_TPB) void k1_mlp(
    const float* __restrict__ x,
    const float* __restrict__ W1,
    const float* __restrict__ b1,
    const float* __restrict__ W2,
    const float* __restrict__ b2,
    const float* __restrict__ W3,
    const float* __restrict__ b3,
    int B)
{
    __shared__ u64 sW1d[IN_DIM * H_DIM];
    __shared__ u64 sB1d[H_DIM];
    __shared__ u64 sW2d[H_DIM * H_DIM];
    __shared__ u64 sB2d[H_DIM];
    __shared__ u64 sW3d[H_DIM];
    __shared__ float sB3;

    const int t = threadIdx.x;
    for (int i = t; i < IN_DIM * H_DIM; i += K1_TPB) sW1d[i] = splat_bits(W1[i]);
    for (int i = t; i < H_DIM * H_DIM; i += K1_TPB) sW2d[i] = splat_bits(W2[i]);
    if (t < H_DIM) {
        sB1d[t] = splat_bits(b1[t]);
        sB2d[t] = splat_bits(b2[t]);
        sW3d[t] = splat_bits(W3[t]);
    }
    if (t == 0) sB3 = b3[0];
    __syncthreads();

    const int rb = (blockIdx.x * K1_TPB + t) * K1_RPT;
    if (rb >= B) return;

    // 2 consecutive rows: 8 consecutive floats, coalesced
    const float4 v0 = *reinterpret_cast<const float4*>(x + 4ll * rb);
    const float4 v1 = *reinterpret_cast<const float4*>(x + 4ll * rb + 4);

    u64 xP[IN_DIM];
    xP[0] = f2_pack(v0.x, v1.x);
    xP[1] = f2_pack(v0.y, v1.y);
    xP[2] = f2_pack(v0.z, v1.z);
    xP[3] = f2_pack(v0.w, v1.w);

    // layer 1 (fully unrolled: h1P must be static register indices)
    u64 h1P[H_DIM];
    #pragma unroll
    for (int j = 0; j < H_DIM; ++j) {
        u64 aP = sB1d[j];
        #pragma unroll
        for (int i = 0; i < IN_DIM; ++i)
            aP = f2_fma(xP[i], sW1d[i * H_DIM + j], aP);
        h1P[j] = f2_relu(aP);
    }

    // layer 2 + output: unroll j by 2 -> 2 independent FFMA2 chains for latency
    u64 yP = f2_pack(sB3, sB3);
    #pragma unroll 2
    for (int j = 0; j < H_DIM; ++j) {
        u64 aP = sB2d[j];
        #pragma unroll
        for (int k = 0; k < H_DIM; ++k)
            aP = f2_fma(h1P[k], sW2d[k * H_DIM + j], aP);
        yP = f2_fma(f2_relu(aP), sW3d[j], yP);
    }

    const float sumPd = __ldg(&g_sumPd);   // broadcast, L1-hit
    const float wc    = __ldg(&g_wcap);

    float y0, y1;
    f2_unpack(yP, y0, y1);
    float2 td;
    td.x = sumPd - wc * y0;
    td.y = sumPd - wc * y1;
    *reinterpret_cast<float2*>(g_td + rb) = td;
}

// ---------------------------------------------------------------------------
// K2: dispatch writer. Thread owns fixed unit-group g=t%25 (cum/pmax in regs).
// Per iteration: 1 LDS + clip + 1 STG.128 through an incremented pointer.
// ---------------------------------------------------------------------------
__global__ __launch_bounds__(K2_TPB) void k2_dispatch(
    const float* __restrict__ Pmax,
    float* __restrict__ out,
    int B)
{
    __shared__ float sCum[N_UNIT];
    __shared__ float sPm[N_UNIT];
    __shared__ float sTd[K2_ROWS];

    const int t = threadIdx.x;
    if (t < N_UNIT) { sCum[t] = g_cum[t]; sPm[t] = Pmax[t]; }

    const int rowbase = blockIdx.x * K2_ROWS;
    if (t < K2_ROWS) {
        const int r = rowbase + t;
        sTd[t] = (r < B) ? g_td[r] : 0.0f;
    }
    __syncthreads();

    const int g  = t % 25;          // unit-group: units [4g, 4g+4)
    const int r0 = t / 25;          // 0..31
    float4 cum4, pm4;
    cum4.x = sCum[4 * g + 0]; cum4.y = sCum[4 * g + 1];
    cum4.z = sCum[4 * g + 2]; cum4.w = sCum[4 * g + 3];
    pm4.x  = sPm[4 * g + 0]; pm4.y = sPm[4 * g + 1];
    pm4.z  = sPm[4 * g + 2]; pm4.w = sPm[4 * g + 3];

    float4* p = reinterpret_cast<float4*>(out) +
                ((long long)(rowbase + r0) * 25 + g);
    int rl = r0;

    #pragma unroll
    for (int k = 0; k < K2_ROWS / 32; ++k) {
        if (rowbase + rl >= B) break;
        const float td = sTd[rl];
        float4 v;
        v.x = fminf(fmaxf(td - cum4.x, 0.0f), pm4.x);
        v.y = fminf(fmaxf(td - cum4.y, 0.0f), pm4.y);
        v.z = fminf(fmaxf(td - cum4.z, 0.0f), pm4.z);
        v.w = fminf(fmaxf(td - cum4.w, 0.0f), pm4.w);
        *p = v;
        rl += 32;
        p  += 32 * 25;              // 32 rows * 25 float4/row
    }
}

extern "C" void kernel_launch(void* const* d_in, const int* in_sizes, int n_in,
                              void* d_out, int out_size) {
    const float* x    = (const float*)d_in[0];
    const float* Cost = (const float*)d_in[1];
    const float* Pmax = (const float*)d_in[2];
    const float* Pd   = (const float*)d_in[3];
    const float* wcap = (const float*)d_in[4];
    const float* W1   = (const float*)d_in[5];
    const float* b1   = (const float*)d_in[6];
    const float* W2   = (const float*)d_in[7];
    const float* b2   = (const float*)d_in[8];
    const float* W3   = (const float*)d_in[9];
    const float* b3   = (const float*)d_in[10];
    float* out = (float*)d_out;

    const int B = in_sizes[0] / IN_DIM;

    k0_prep<<<1, 128>>>(Cost, Pmax, Pd, wcap);

    const int grid1 = (B + K1_TPB * K1_RPT - 1) / (K1_TPB * K1_RPT);
    k1_mlp<<<grid1, K1_TPB>>>(x, W1, b1, W2, b2, W3, b3, B);

    const int grid2 = (B + K2_ROWS - 1) / K2_ROWS;
    k2_dispatch<<<grid2, K2_TPB>>>(Pmax, out, B);
}